// round 15
// baseline (speedup 1.0000x reference)
#include <cuda_runtime.h>
#include <cuda_fp16.h>
#include <cstdint>

// y = conv2d(x[1,512,512,16], w[3,3,16,64], SAME); pot = y + old
// spike = pot >= 1; new_pot = spike ? 0 : pot
// d_out: [spikes 512*512*64][new_pot 512*512*64]
//
// HMMA implicit GEMM (mma.sync m16n8k16 f16, f32 acc), split-2 fp16 emulation.
// Warp tile 32 px x 32 couts; block = 128 px x 64 couts; 3 CTAs/SM (RF-capped).
// R15: oldp preloaded into accumulators (epilogue LDG latency hidden behind
// the whole mainloop); STS.64 staging.

#define HH 512
#define WW 512
#define CIN 16
#define COUT 64

#define B_BYTES (9 * 2 * 2 * 2 * 32 * 16) /* 36864 */
#define A_PITCH 48                     /* bytes per pixel-row: 16 ci f16 + pad */
#define A_BUF   (130 * A_PITCH)        /* 6240 per (split,row) buffer */
#define A_OFF   B_BYTES
#define SMEM_TOTAL (A_OFF + 6 * A_BUF) /* 74304 ; x3 CTAs = 222912 <= 228KB */

// B fragments: [tap][cbhalf][split][ntpair][lane]{16B = 2 frags}
__device__ static uint2 g_Bfrag[9 * 2 * 2 * 2 * 32 * 2];

__device__ __forceinline__ uint32_t smem_u32(const void* p) {
    uint32_t a;
    asm("{ .reg .u64 t; cvta.to.shared.u64 t, %1; cvt.u32.u64 %0, t; }"
        : "=r"(a) : "l"(p));
    return a;
}
__device__ __forceinline__ uint32_t pack_h2(float a, float b) {
    __half2 h = __floats2half2_rn(a, b);
    return *(uint32_t*)&h;
}
__device__ __forceinline__ float h_rt(float v) {
    return __half2float(__float2half_rn(v));
}
__device__ __forceinline__ void ldmatrix_x4(uint32_t* r, uint32_t addr) {
    asm volatile("ldmatrix.sync.aligned.m8n8.x4.shared.b16 {%0,%1,%2,%3}, [%4];"
                 : "=r"(r[0]), "=r"(r[1]), "=r"(r[2]), "=r"(r[3]) : "r"(addr));
}
__device__ __forceinline__ void mma_f16(float* d, const uint32_t* a, uint2 b) {
    asm volatile(
        "mma.sync.aligned.m16n8k16.row.col.f32.f16.f16.f32 "
        "{%0,%1,%2,%3}, {%4,%5,%6,%7}, {%8,%9}, {%0,%1,%2,%3};"
        : "+f"(d[0]), "+f"(d[1]), "+f"(d[2]), "+f"(d[3])
        : "r"(a[0]), "r"(a[1]), "r"(a[2]), "r"(a[3]), "r"(b.x), "r"(b.y));
}
__device__ __forceinline__ void cp_async16(uint32_t dst, const void* src) {
    asm volatile("cp.async.cg.shared.global [%0], [%1], 16;"
                 :: "r"(dst), "l"(src) : "memory");
}

// ---- prep: B fragments (hi/lo) in m16n8k16 .col layout, LDS.128-friendly ----
__global__ void prep_weights(const float* __restrict__ wt) {
    int idx = blockIdx.x * 256 + threadIdx.x;   // one uint2 each; 4608 total
    if (idx >= 9 * 2 * 2 * 2 * 32 * 2) return;
    int ni   = idx & 1;
    int lane = (idx >> 1) & 31;
    int np   = (idx >> 6) & 1;
    int s    = (idx >> 7) & 1;
    int cbh  = (idx >> 8) & 1;
    int tap  = idx >> 9;
    int nt = cbh * 4 + np * 2 + ni;       // global n-tile 0..7
    int g = lane >> 2, tg = lane & 3;
    int n = nt * 8 + g;
    float w[4];
    int kk[4] = {tg * 2, tg * 2 + 1, tg * 2 + 8, tg * 2 + 9};
    #pragma unroll
    for (int j = 0; j < 4; j++) {
        float wv = wt[(tap * 16 + kk[j]) * 64 + n];
        w[j] = s == 0 ? wv : (wv - h_rt(wv));
    }
    g_Bfrag[idx] = make_uint2(pack_h2(w[0], w[1]), pack_h2(w[2], w[3]));
}

// ---- main kernel ----
__global__ void __launch_bounds__(256, 3)
snn_conv_mma(const float* __restrict__ in, const float* __restrict__ oldp,
             float* __restrict__ out_spk, float* __restrict__ out_pot) {
    extern __shared__ char smem[];
    const uint32_t sb = smem_u32(smem);
    const int tid = threadIdx.x;
    const int wid = tid >> 5;
    const int lane = tid & 31;
    const int x0 = blockIdx.x * 128;
    const int y  = blockIdx.y;

    // ---- stage B fragments via cp.async ----
    #pragma unroll
    for (int i = tid; i < B_BYTES / 16; i += 256)
        cp_async16(sb + i * 16, (const char*)g_Bfrag + i * 16);
    asm volatile("cp.async.commit_group;" ::: "memory");

    // warp tile indices (needed early for the oldp preload)
    const int m0 = (wid >> 1) * 32;
    const int cbh = wid & 1;
    const int cb = cbh * 32;
    const int g = lane >> 2, tg = lane & 3;

    // ---- preload old potentials INTO accumulators (latency hidden behind
    //      staging + the whole mainloop; acc layout matches epilogue) ----
    float acc[2][4][4];    // [px-half][n-tile][frag]
    int ebase[2][2];
    #pragma unroll
    for (int t = 0; t < 2; t++) {
        int b0 = (y * WW + x0 + m0 + t * 16 + g) * COUT + cb + tg * 2;
        int b1 = b0 + 8 * COUT;
        ebase[t][0] = b0;
        ebase[t][1] = b1;
        #pragma unroll
        for (int nt = 0; nt < 4; nt++) {
            float2 o0 = __ldcs((const float2*)(oldp + b0 + nt * 8));
            float2 o1 = __ldcs((const float2*)(oldp + b1 + nt * 8));
            acc[t][nt][0] = o0.x;  acc[t][nt][1] = o0.y;
            acc[t][nt][2] = o1.x;  acc[t][nt][3] = o1.y;
        }
    }

    // ---- stage A: 3 source rows x 130 px x 16 ci, split hi/lo fp16 ----
    for (int i = tid; i < 3 * 130 * 4; i += 256) {
        int q = i & 3;
        int t = i >> 2;
        int p = t % 130;          // buffer row (gx = x0 + p - 1)
        int r = t / 130;          // source row (gy = y + r - 1)
        int gx = x0 + p - 1, gy = y + r - 1;
        float4 v = make_float4(0.f, 0.f, 0.f, 0.f);
        if ((unsigned)gx < WW && (unsigned)gy < HH)
            v = *(const float4*)(in + (gy * WW + gx) * CIN + q * 4);
        float hx = h_rt(v.x), hy = h_rt(v.y);
        float hz = h_rt(v.z), hw = h_rt(v.w);
        char* rh = smem + A_OFF + r * A_BUF + p * A_PITCH + q * 8;
        char* rl = rh + 3 * A_BUF;
        *(uint2*)(rh) = make_uint2(pack_h2(v.x, v.y), pack_h2(v.z, v.w));
        *(uint2*)(rl) = make_uint2(pack_h2(v.x - hx, v.y - hy),
                                   pack_h2(v.z - hz, v.w - hw));
    }
    asm volatile("cp.async.wait_all;" ::: "memory");
    __syncthreads();

    const uint32_t rowsel = (lane & 7) + ((lane >> 3) & 1) * 8;
    const uint32_t koff = (lane >> 4) * 16;

    #pragma unroll
    for (int tt = 0; tt < 9; tt++) {
        int tap = tt + wid;                   // warp-staggered tap order
        if (tap >= 9) tap -= 9;
        const int dy = tap / 3, dx = tap - dy * 3;

        // ALL loads of this tap first (max MLP)
        const char* bb = smem + (tap * 2 + cbh) * 2048 + lane * 16;
        uint4 h01 = *(const uint4*)(bb);
        uint4 h23 = *(const uint4*)(bb + 512);
        uint4 l01 = *(const uint4*)(bb + 1024);
        uint4 l23 = *(const uint4*)(bb + 1536);

        uint32_t abase = sb + A_OFF + dy * A_BUF +
                         (m0 + dx + rowsel) * A_PITCH + koff;
        uint32_t ah0[4], ah1[4], al0[4], al1[4];
        ldmatrix_x4(ah0, abase);
        ldmatrix_x4(al0, abase + 3 * A_BUF);
        ldmatrix_x4(ah1, abase + 16 * A_PITCH);
        ldmatrix_x4(al1, abase + 3 * A_BUF + 16 * A_PITCH);

        uint2 bh[4] = {make_uint2(h01.x, h01.y), make_uint2(h01.z, h01.w),
                       make_uint2(h23.x, h23.y), make_uint2(h23.z, h23.w)};
        uint2 bl[4] = {make_uint2(l01.x, l01.y), make_uint2(l01.z, l01.w),
                       make_uint2(l23.x, l23.y), make_uint2(l23.z, l23.w)};

        // product-major, cross-half interleave: same-acc RAW distance = 8
        #pragma unroll
        for (int nt = 0; nt < 4; nt++) mma_f16(acc[0][nt], ah0, bh[nt]);
        #pragma unroll
        for (int nt = 0; nt < 4; nt++) mma_f16(acc[1][nt], ah1, bh[nt]);
        #pragma unroll
        for (int nt = 0; nt < 4; nt++) mma_f16(acc[0][nt], ah0, bl[nt]);
        #pragma unroll
        for (int nt = 0; nt < 4; nt++) mma_f16(acc[1][nt], ah1, bl[nt]);
        #pragma unroll
        for (int nt = 0; nt < 4; nt++) mma_f16(acc[0][nt], al0, bh[nt]);
        #pragma unroll
        for (int nt = 0; nt < 4; nt++) mma_f16(acc[1][nt], al1, bh[nt]);
    }

    // ---- epilogue: threshold + reset + streaming stores (no loads left) ----
    #pragma unroll
    for (int t = 0; t < 2; t++) {
        #pragma unroll
        for (int half = 0; half < 2; half++) {
            int base = ebase[t][half];
            #pragma unroll
            for (int nt = 0; nt < 4; nt++) {
                float v0 = acc[t][nt][half * 2 + 0];
                float v1 = acc[t][nt][half * 2 + 1];
                bool f0 = v0 >= 1.f, f1 = v1 >= 1.f;
                __stcs((float2*)(out_spk + base + nt * 8),
                       make_float2(f0 ? 1.f : 0.f, f1 ? 1.f : 0.f));
                __stcs((float2*)(out_pot + base + nt * 8),
                       make_float2(f0 ? 0.f : v0, f1 ? 0.f : v1));
            }
        }
    }
}

extern "C" void kernel_launch(void* const* d_in, const int* in_sizes, int n_in,
                              void* d_out, int out_size) {
    const float* in   = (const float*)d_in[0];   // [1,512,512,16]
    const float* wt   = (const float*)d_in[1];   // [3,3,16,64]
    const float* oldp = (const float*)d_in[2];   // [1,512,512,64]
    float* spk = (float*)d_out;
    float* pot = (float*)d_out + in_sizes[2];

    prep_weights<<<(9 * 2 * 2 * 2 * 32 * 2 + 255) / 256, 256>>>(wt);

    cudaFuncSetAttribute(snn_conv_mma,
                         cudaFuncAttributeMaxDynamicSharedMemorySize, SMEM_TOTAL);
    dim3 grid(WW / 128, HH);   // 4 x 512
    snn_conv_mma<<<grid, 256, SMEM_TOTAL>>>(in, oldp, spk, pot);
}

// round 16
// speedup vs baseline: 1.1493x; 1.1493x over previous
#include <cuda_runtime.h>
#include <cuda_fp16.h>
#include <cstdint>

// y = conv2d(x[1,512,512,16], w[3,3,16,64], SAME); pot = y + old
// spike = pot >= 1; new_pot = spike ? 0 : pot
// d_out: [spikes 512*512*64][new_pot 512*512*64]
//
// HMMA implicit GEMM (mma.sync m16n8k16 f16, f32 acc), split-2 fp16 emulation.
// Warp tile 32 px x 32 couts; block = 128 px x 64 couts; 3 CTAs/SM (RF-capped).
// R16 = R14 + cout permutation in the B table so each thread's 8 output
// channels are contiguous -> 128-bit epilogue loads/stores.

#define HH 512
#define WW 512
#define CIN 16
#define COUT 64

#define B_BYTES (9 * 2 * 2 * 2 * 32 * 16) /* 36864 */
#define A_PITCH 48                     /* bytes per pixel-row: 16 ci f16 + pad */
#define A_BUF   (130 * A_PITCH)        /* 6240 per (split,row) buffer */
#define A_OFF   B_BYTES
#define SMEM_TOTAL (A_OFF + 6 * A_BUF) /* 74304 ; x3 CTAs = 222912 <= 228KB */

// B fragments: [tap][cbhalf][split][ntpair][lane]{16B = 2 frags}
__device__ static uint2 g_Bfrag[9 * 2 * 2 * 2 * 32 * 2];

__device__ __forceinline__ uint32_t smem_u32(const void* p) {
    uint32_t a;
    asm("{ .reg .u64 t; cvta.to.shared.u64 t, %1; cvt.u32.u64 %0, t; }"
        : "=r"(a) : "l"(p));
    return a;
}
__device__ __forceinline__ uint32_t pack_h2(float a, float b) {
    __half2 h = __floats2half2_rn(a, b);
    return *(uint32_t*)&h;
}
__device__ __forceinline__ float h_rt(float v) {
    return __half2float(__float2half_rn(v));
}
__device__ __forceinline__ void ldmatrix_x4(uint32_t* r, uint32_t addr) {
    asm volatile("ldmatrix.sync.aligned.m8n8.x4.shared.b16 {%0,%1,%2,%3}, [%4];"
                 : "=r"(r[0]), "=r"(r[1]), "=r"(r[2]), "=r"(r[3]) : "r"(addr));
}
__device__ __forceinline__ void mma_f16(float* d, const uint32_t* a, uint2 b) {
    asm volatile(
        "mma.sync.aligned.m16n8k16.row.col.f32.f16.f16.f32 "
        "{%0,%1,%2,%3}, {%4,%5,%6,%7}, {%8,%9}, {%0,%1,%2,%3};"
        : "+f"(d[0]), "+f"(d[1]), "+f"(d[2]), "+f"(d[3])
        : "r"(a[0]), "r"(a[1]), "r"(a[2]), "r"(a[3]), "r"(b.x), "r"(b.y));
}
__device__ __forceinline__ void cp_async16(uint32_t dst, const void* src) {
    asm volatile("cp.async.cg.shared.global [%0], [%1], 16;"
                 :: "r"(dst), "l"(src) : "memory");
}

// ---- prep: B fragments (hi/lo), m16n8k16 .col layout, PERMUTED couts ----
// B column j of n-tile nt (within cout half cbh) holds physical cout:
//   cb + (j>>1)*8 + (nt&3)*2 + (j&1)
// => C-fragment thread (tg) holds contiguous couts cb + tg*8 .. +7.
__global__ void prep_weights(const float* __restrict__ wt) {
    int idx = blockIdx.x * 256 + threadIdx.x;   // one uint2 each; 4608 total
    if (idx >= 9 * 2 * 2 * 2 * 32 * 2) return;
    int ni   = idx & 1;
    int lane = (idx >> 1) & 31;
    int np   = (idx >> 6) & 1;
    int s    = (idx >> 7) & 1;
    int cbh  = (idx >> 8) & 1;
    int tap  = idx >> 9;
    int ntl = np * 2 + ni;                // local n-tile 0..3 within half
    int j = lane >> 2, tg = lane & 3;     // j = B column within tile
    int n = cbh * 32 + ((j >> 1) << 3) + (ntl << 1) + (j & 1);  // permuted cout
    float w[4];
    int kk[4] = {tg * 2, tg * 2 + 1, tg * 2 + 8, tg * 2 + 9};
    #pragma unroll
    for (int jj = 0; jj < 4; jj++) {
        float wv = wt[(tap * 16 + kk[jj]) * 64 + n];
        w[jj] = s == 0 ? wv : (wv - h_rt(wv));
    }
    g_Bfrag[idx] = make_uint2(pack_h2(w[0], w[1]), pack_h2(w[2], w[3]));
}

// ---- main kernel ----
__global__ void __launch_bounds__(256, 3)
snn_conv_mma(const float* __restrict__ in, const float* __restrict__ oldp,
             float* __restrict__ out_spk, float* __restrict__ out_pot) {
    extern __shared__ char smem[];
    const uint32_t sb = smem_u32(smem);
    const int tid = threadIdx.x;
    const int wid = tid >> 5;
    const int lane = tid & 31;
    const int x0 = blockIdx.x * 128;
    const int y  = blockIdx.y;

    // ---- stage B fragments via cp.async ----
    #pragma unroll
    for (int i = tid; i < B_BYTES / 16; i += 256)
        cp_async16(sb + i * 16, (const char*)g_Bfrag + i * 16);
    asm volatile("cp.async.commit_group;" ::: "memory");

    // ---- stage A: 3 source rows x 130 px x 16 ci, split hi/lo fp16 ----
    for (int i = tid; i < 3 * 130 * 4; i += 256) {
        int q = i & 3;
        int t = i >> 2;
        int p = t % 130;          // buffer row (gx = x0 + p - 1)
        int r = t / 130;          // source row (gy = y + r - 1)
        int gx = x0 + p - 1, gy = y + r - 1;
        float4 v = make_float4(0.f, 0.f, 0.f, 0.f);
        if ((unsigned)gx < WW && (unsigned)gy < HH)
            v = *(const float4*)(in + (gy * WW + gx) * CIN + q * 4);
        float hx = h_rt(v.x), hy = h_rt(v.y);
        float hz = h_rt(v.z), hw = h_rt(v.w);
        char* rh = smem + A_OFF + r * A_BUF + p * A_PITCH + q * 8;
        char* rl = rh + 3 * A_BUF;
        *(uint2*)(rh) = make_uint2(pack_h2(v.x, v.y), pack_h2(v.z, v.w));
        *(uint2*)(rl) = make_uint2(pack_h2(v.x - hx, v.y - hy),
                                   pack_h2(v.z - hz, v.w - hw));
    }
    asm volatile("cp.async.wait_all;" ::: "memory");
    __syncthreads();

    // warp tile: pixels m0..m0+31, couts cb..cb+31
    const int m0 = (wid >> 1) * 32;
    const int cbh = wid & 1;
    const uint32_t rowsel = (lane & 7) + ((lane >> 3) & 1) * 8;
    const uint32_t koff = (lane >> 4) * 16;

    float acc[2][4][4];    // [px-half][n-tile][frag]
    #pragma unroll
    for (int t = 0; t < 2; t++)
        #pragma unroll
        for (int nt = 0; nt < 4; nt++)
            #pragma unroll
            for (int j = 0; j < 4; j++) acc[t][nt][j] = 0.f;

    #pragma unroll
    for (int tt = 0; tt < 9; tt++) {
        int tap = tt + wid;                   // warp-staggered tap order
        if (tap >= 9) tap -= 9;
        const int dy = tap / 3, dx = tap - dy * 3;

        // ALL loads of this tap first (max MLP)
        const char* bb = smem + (tap * 2 + cbh) * 2048 + lane * 16;
        uint4 h01 = *(const uint4*)(bb);
        uint4 h23 = *(const uint4*)(bb + 512);
        uint4 l01 = *(const uint4*)(bb + 1024);
        uint4 l23 = *(const uint4*)(bb + 1536);

        uint32_t abase = sb + A_OFF + dy * A_BUF +
                         (m0 + dx + rowsel) * A_PITCH + koff;
        uint32_t ah0[4], ah1[4], al0[4], al1[4];
        ldmatrix_x4(ah0, abase);
        ldmatrix_x4(al0, abase + 3 * A_BUF);
        ldmatrix_x4(ah1, abase + 16 * A_PITCH);
        ldmatrix_x4(al1, abase + 3 * A_BUF + 16 * A_PITCH);

        uint2 bh[4] = {make_uint2(h01.x, h01.y), make_uint2(h01.z, h01.w),
                       make_uint2(h23.x, h23.y), make_uint2(h23.z, h23.w)};
        uint2 bl[4] = {make_uint2(l01.x, l01.y), make_uint2(l01.z, l01.w),
                       make_uint2(l23.x, l23.y), make_uint2(l23.z, l23.w)};

        // product-major, cross-half interleave: same-acc RAW distance = 8
        #pragma unroll
        for (int nt = 0; nt < 4; nt++) mma_f16(acc[0][nt], ah0, bh[nt]);
        #pragma unroll
        for (int nt = 0; nt < 4; nt++) mma_f16(acc[1][nt], ah1, bh[nt]);
        #pragma unroll
        for (int nt = 0; nt < 4; nt++) mma_f16(acc[0][nt], ah0, bl[nt]);
        #pragma unroll
        for (int nt = 0; nt < 4; nt++) mma_f16(acc[1][nt], ah1, bl[nt]);
        #pragma unroll
        for (int nt = 0; nt < 4; nt++) mma_f16(acc[0][nt], al0, bh[nt]);
        #pragma unroll
        for (int nt = 0; nt < 4; nt++) mma_f16(acc[1][nt], al1, bh[nt]);
    }

    // ---- epilogue: contiguous 8-cout span per thread -> 128-bit ops ----
    const int g = lane >> 2, tg = lane & 3;
    const int cb = cbh * 32;
    #pragma unroll
    for (int t = 0; t < 2; t++) {
        int base0 = (y * WW + x0 + m0 + t * 16 + g) * COUT + cb + tg * 8;
        int base1 = base0 + 8 * COUT;   // rows +8 (half 1)
        float4 oa0 = __ldcs((const float4*)(oldp + base0));
        float4 ob0 = __ldcs((const float4*)(oldp + base0 + 4));
        float4 oa1 = __ldcs((const float4*)(oldp + base1));
        float4 ob1 = __ldcs((const float4*)(oldp + base1 + 4));
        #pragma unroll
        for (int half = 0; half < 2; half++) {
            int base = half ? base1 : base0;
            float4 oa = half ? oa1 : oa0;
            float4 ob = half ? ob1 : ob0;
            int h2 = half * 2;
            float v0 = acc[t][0][h2 + 0] + oa.x;
            float v1 = acc[t][0][h2 + 1] + oa.y;
            float v2 = acc[t][1][h2 + 0] + oa.z;
            float v3 = acc[t][1][h2 + 1] + oa.w;
            float v4 = acc[t][2][h2 + 0] + ob.x;
            float v5 = acc[t][2][h2 + 1] + ob.y;
            float v6 = acc[t][3][h2 + 0] + ob.z;
            float v7 = acc[t][3][h2 + 1] + ob.w;
            bool f0 = v0 >= 1.f, f1 = v1 >= 1.f, f2 = v2 >= 1.f, f3 = v3 >= 1.f;
            bool f4 = v4 >= 1.f, f5 = v5 >= 1.f, f6 = v6 >= 1.f, f7 = v7 >= 1.f;
            __stcs((float4*)(out_spk + base),
                   make_float4(f0 ? 1.f : 0.f, f1 ? 1.f : 0.f,
                               f2 ? 1.f : 0.f, f3 ? 1.f : 0.f));
            __stcs((float4*)(out_spk + base + 4),
                   make_float4(f4 ? 1.f : 0.f, f5 ? 1.f : 0.f,
                               f6 ? 1.f : 0.f, f7 ? 1.f : 0.f));
            __stcs((float4*)(out_pot + base),
                   make_float4(f0 ? 0.f : v0, f1 ? 0.f : v1,
                               f2 ? 0.f : v2, f3 ? 0.f : v3));
            __stcs((float4*)(out_pot + base + 4),
                   make_float4(f4 ? 0.f : v4, f5 ? 0.f : v5,
                               f6 ? 0.f : v6, f7 ? 0.f : v7));
        }
    }
}

extern "C" void kernel_launch(void* const* d_in, const int* in_sizes, int n_in,
                              void* d_out, int out_size) {
    const float* in   = (const float*)d_in[0];   // [1,512,512,16]
    const float* wt   = (const float*)d_in[1];   // [3,3,16,64]
    const float* oldp = (const float*)d_in[2];   // [1,512,512,64]
    float* spk = (float*)d_out;
    float* pot = (float*)d_out + in_sizes[2];

    prep_weights<<<(9 * 2 * 2 * 2 * 32 * 2 + 255) / 256, 256>>>(wt);

    cudaFuncSetAttribute(snn_conv_mma,
                         cudaFuncAttributeMaxDynamicSharedMemorySize, SMEM_TOTAL);
    dim3 grid(WW / 128, HH);   // 4 x 512
    snn_conv_mma<<<grid, 256, SMEM_TOTAL>>>(in, oldp, spk, pot);
}